// round 8
// baseline (speedup 1.0000x reference)
#include <cuda_runtime.h>
#include <cuda_bf16.h>
#include <math.h>
#include <stdint.h>

#define NWG   256
#define NP    128
#define NITER 3
#define TBR   4

#define HALF_G    0.07853981633974483f   // 0.5 * 0.05 * pi
#define HALF_PHIB 1.5707963267948966f    // 0.5 * pi
#define SQ09      0.9486832980505138f    // sqrt(1 - 0.1)

// GEMM tiling
#define BM 128
#define BN 128
#define BK 16
#define NKCH 32                          // 512 / 16
#define BLKB 4096                        // bytes per plane block (128 rows x 32B)
#define STG_BYTES 16384                  // Ah|Al|Bh|Bl = 16KB per stage
#define NSTG 6
#define SMEM_DYN (NSTG * STG_BYTES)      // 96KB
#define LOOKAHEAD 4

// Tiled global layouts (pre-swizzled 4KB blocks = 2048 bf16):
//   A: [mtile 64][kch 32][plane 2][2048]   B: [ntile 4][kch 32][plane 2][2048]
#define A_ELEMS (64 * 32 * 2 * 2048)
#define B_ELEMS (4 * 32 * 2 * 2048)

// ---------------- device scratch (no allocs allowed) ----------------
__device__ float4 g_coef[NITER * NWG * NP * 2];
__device__ float  g_Rre[NITER * NWG * NWG];
__device__ float  g_Rim[NITER * NWG * NWG];
__device__ __nv_bfloat16 gBt[NITER * B_ELEMS];
__device__ __nv_bfloat16 gAt[2][A_ELEMS];
__device__ float gV[8192 * 256];

// ---------------- PTX helpers ----------------
__device__ __forceinline__ uint32_t smem_u32(const void* p) {
    return (uint32_t)__cvta_generic_to_shared(p);
}

#define LDSM4(r, addr)                                                         \
    asm volatile("ldmatrix.sync.aligned.m8n8.x4.shared.b16 {%0,%1,%2,%3}, [%4];" \
        : "=r"((r)[0]), "=r"((r)[1]), "=r"((r)[2]), "=r"((r)[3]) : "r"(addr))

__device__ __forceinline__ void mma_bf16(float* d, const uint32_t* a,
                                         uint32_t b0, uint32_t b1) {
    asm volatile(
        "mma.sync.aligned.m16n8k16.row.col.f32.bf16.bf16.f32 "
        "{%0,%1,%2,%3}, {%4,%5,%6,%7}, {%8,%9}, {%0,%1,%2,%3};"
        : "+f"(d[0]), "+f"(d[1]), "+f"(d[2]), "+f"(d[3])
        : "r"(a[0]), "r"(a[1]), "r"(a[2]), "r"(a[3]), "r"(b0), "r"(b1));
}

__device__ __forceinline__ void bulk_g2s(uint32_t dst, const void* src,
                                         uint32_t bytes, uint32_t mb) {
    asm volatile(
        "cp.async.bulk.shared::cluster.global.mbarrier::complete_tx::bytes "
        "[%0], [%1], %2, [%3];"
        :: "r"(dst), "l"(src), "r"(bytes), "r"(mb) : "memory");
}
#define MBAR_INIT(mb, n)  asm volatile("mbarrier.init.shared.b64 [%0], %1;" :: "r"(mb), "r"((uint32_t)(n)) : "memory")
#define MBAR_EXPECT_TX(mb, tx) asm volatile("mbarrier.arrive.expect_tx.shared.b64 _, [%0], %1;" :: "r"(mb), "r"((uint32_t)(tx)) : "memory")
#define MBAR_ARRIVE(mb)   asm volatile("mbarrier.arrive.shared.b64 _, [%0];" :: "r"(mb) : "memory")

#define MBAR_WAIT(mb, par) do {                                                    \
    uint32_t _mb = (mb); uint32_t _p = (par); uint32_t _done;                      \
    asm volatile("{\n\t.reg .pred p;\n\t"                                          \
        "mbarrier.try_wait.parity.acquire.cta.shared::cta.b64 p, [%1], %2;\n\t"    \
        "selp.b32 %0, 1, 0, p;\n\t}"                                               \
        : "=r"(_done) : "r"(_mb), "r"(_p) : "memory");                             \
    if (!_done) {                                                                  \
        asm volatile("{\n\t.reg .pred P1;\n\t"                                     \
        "WL_%=:\n\t"                                                               \
        "mbarrier.try_wait.parity.acquire.cta.shared::cta.b64 P1, [%0], %1, 0x989680;\n\t" \
        "@P1 bra.uni WD_%=;\n\t"                                                   \
        "bra.uni WL_%=;\n\t"                                                       \
        "WD_%=:\n\t}" :: "r"(_mb), "r"(_p) : "memory");                            \
    } } while (0)

// swizzled byte offset within a 4KB plane block (row 0..127, 16B chunk c 0..1)
__device__ __forceinline__ uint32_t swz(int row, int c) {
    return (uint32_t)(row * 32 + ((c ^ ((row >> 2) & 1)) << 4));
}

// ============================================================
// Kernel 1: fold theta/phi into 2x2 complex MZI matrices
// ============================================================
__global__ void coef_kernel(const float* __restrict__ theta,
                            const float* __restrict__ phi) {
    int t = blockIdx.x * blockDim.x + threadIdx.x;
    const int total = NITER * NWG * NP;
    if (t >= total) return;
    int pair  = t % NP;
    int layer = (t / NP) % NWG;

    float4 c01, c23;
    if ((layer & 1) && pair == NP - 1) {
        c01 = make_float4(1.f, 0.f, 0.f, 0.f);
        c23 = make_float4(0.f, 0.f, 1.f, 0.f);
    } else {
        float h = 0.5f * theta[t];
        float s, c;  sincosf(h, &s, &c);
        float sp, cp; sincosf(phi[t], &sp, &cp);
        float pre_r = -s, pre_i = c;
        float pe_r = pre_r * cp - pre_i * sp;
        float pe_i = pre_r * sp + pre_i * cp;
        c01 = make_float4(pe_r * s,  pe_i * s,   pre_r * c,  pre_i * c);
        c23 = make_float4(pe_r * c,  pe_i * c,  -pre_r * s, -pre_i * s);
    }
    g_coef[2 * t]     = c01;
    g_coef[2 * t + 1] = c23;
}

// ============================================================
// Kernel 2: build R via identity basis. grid (64, 3), block 512.
// ============================================================
__global__ void build_R_kernel(const float* __restrict__ gamma) {
    __shared__ float x0r[TBR][NP], x0i[TBR][NP], x1r[TBR][NP], x1i[TBR][NP];
    const int iter = blockIdx.y;
    const int p = threadIdx.x & (NP - 1);
    const int r = threadIdx.x >> 7;
    const int gj = blockIdx.x * TBR + r;

    x0r[r][p] = (2 * p     == gj) ? 1.f : 0.f;  x0i[r][p] = 0.f;
    x1r[r][p] = (2 * p + 1 == gj) ? 1.f : 0.f;  x1i[r][p] = 0.f;
    __syncthreads();

    const float4* cbase = g_coef + (size_t)iter * NWG * NP * 2;
    for (int l = 0; l < NWG; l++) {
        float4 c01 = cbase[(l * NP + p) * 2];
        float4 c23 = cbase[(l * NP + p) * 2 + 1];
        float Ar = c01.x, Ai = c01.y, Br = c01.z, Bi = c01.w;
        float Cr = c23.x, Ci = c23.y, Dr = c23.z, Di = c23.w;
        if (!(l & 1)) {
            float ar = x0r[r][p], ai = x0i[r][p];
            float br = x1r[r][p], bi = x1i[r][p];
            x0r[r][p] = Ar*ar - Ai*ai + Br*br - Bi*bi;
            x0i[r][p] = Ar*ai + Ai*ar + Br*bi + Bi*br;
            x1r[r][p] = Cr*ar - Ci*ai + Dr*br - Di*bi;
            x1i[r][p] = Cr*ai + Ci*ar + Dr*bi + Di*br;
        } else if (p < NP - 1) {
            float ar = x1r[r][p],     ai = x1i[r][p];
            float br = x0r[r][p + 1], bi = x0i[r][p + 1];
            float y0r = Ar*ar - Ai*ai + Br*br - Bi*bi;
            float y0i = Ar*ai + Ai*ar + Br*bi + Bi*br;
            float y1r = Cr*ar - Ci*ai + Dr*br - Di*bi;
            float y1i = Cr*ai + Ci*ar + Dr*bi + Di*br;
            x1r[r][p] = y0r;     x1i[r][p] = y0i;
            x0r[r][p + 1] = y1r; x0i[r][p + 1] = y1i;
        }
        __syncthreads();
    }

    float s0, c0, s1, c1;
    sincosf(gamma[iter * NWG + 2 * p],     &s0, &c0);
    sincosf(gamma[iter * NWG + 2 * p + 1], &s1, &c1);
    size_t rowoff = ((size_t)iter * NWG + gj) * NWG;
    float xr = x0r[r][p], xi = x0i[r][p];
    g_Rre[rowoff + 2 * p] = xr * c0 - xi * s0;
    g_Rim[rowoff + 2 * p] = xr * s0 + xi * c0;
    xr = x1r[r][p]; xi = x1i[r][p];
    g_Rre[rowoff + 2 * p + 1] = xr * c1 - xi * s1;
    g_Rim[rowoff + 2 * p + 1] = xr * s1 + xi * c1;
}

// ============================================================
// Kernel 3: pack W^T into tiled, pre-swizzled bf16 hi/lo blocks.
// thread: (it, n, kq): kq indexes a 16B group (8 k values).
// ============================================================
__global__ void pack_W_kernel() {
    int t = blockIdx.x * blockDim.x + threadIdx.x;
    if (t >= NITER * 512 * 64) return;
    int kq = t & 63;
    int n  = (t >> 6) & 511;
    int it = t >> 15;
    int c = n >> 1, nb = n & 1;

    __align__(16) __nv_bfloat16 hb[8], lb[8];
    #pragma unroll
    for (int q = 0; q < 8; q++) {
        int k = kq * 8 + q;
        int a = k >> 1, kb = k & 1;
        size_t ri = ((size_t)it * NWG + a) * NWG + c;
        float val;
        if (kb == nb)      val = g_Rre[ri];
        else if (kb == 1)  val = -g_Rim[ri];
        else               val = g_Rim[ri];
        __nv_bfloat16 h = __float2bfloat16_rn(val);
        hb[q] = h;
        lb[q] = __float2bfloat16_rn(val - __bfloat162float(h));
    }
    int ntile = n >> 7, r = n & 127;
    int kch = kq >> 1, cw = kq & 1;
    size_t base = (size_t)it * B_ELEMS + (size_t)((ntile * 32 + kch) * 2) * 2048;
    size_t off = (size_t)r * 16 + ((cw ^ ((r >> 2) & 1)) << 3);
    *(uint4*)(gBt + base + off)        = *(const uint4*)hb;
    *(uint4*)(gBt + base + 2048 + off) = *(const uint4*)lb;
}

// ============================================================
// Kernel 4: prep A0 into tiled, pre-swizzled layout.
// ============================================================
__global__ void prep_A_kernel(const float* __restrict__ xr,
                              const float* __restrict__ xi) {
    int t = blockIdx.x * blockDim.x + threadIdx.x;
    if (t >= 8192 * 64) return;
    int cq = t & 63, m = t >> 6;
    float4 vr = *(const float4*)(xr + (size_t)m * 256 + cq * 4);
    float4 vi = *(const float4*)(xi + (size_t)m * 256 + cq * 4);
    float re[4] = { vr.x, vr.y, vr.z, vr.w };
    float im[4] = { vi.x, vi.y, vi.z, vi.w };
    __align__(16) __nv_bfloat16 hb[8], lb[8];
    #pragma unroll
    for (int q = 0; q < 4; q++) {
        __nv_bfloat16 h = __float2bfloat16_rn(re[q]);
        hb[2 * q] = h;  lb[2 * q] = __float2bfloat16_rn(re[q] - __bfloat162float(h));
        h = __float2bfloat16_rn(im[q]);
        hb[2 * q + 1] = h;  lb[2 * q + 1] = __float2bfloat16_rn(im[q] - __bfloat162float(h));
    }
    int mtile = m >> 7, r = m & 127;
    int kch = cq >> 1, cw = cq & 1;
    size_t base = (size_t)((mtile * 32 + kch) * 2) * 2048;
    size_t off = (size_t)r * 16 + ((cw ^ ((r >> 2) & 1)) << 3);
    *(uint4*)(gAt[0] + base + off)        = *(const uint4*)hb;
    *(uint4*)(gAt[0] + base + 2048 + off) = *(const uint4*)lb;
}

// ============================================================
// Kernel 5: bf16 split-2 GEMM. Free-running warps, full/empty
// mbarrier ring (6 stages x 16KB), NO per-chunk __syncthreads.
// grid (64, 4), 256 threads, 2 CTAs/SM.
// ============================================================
__global__ void __launch_bounds__(256, 2) gemm_kernel(int iter) {
    extern __shared__ char smraw[];
    __shared__ __align__(8) unsigned long long s_full[NSTG], s_empty[NSTG];
    const uint32_t smem_u = (uint32_t)__cvta_generic_to_shared(smraw);

    const int tid = threadIdx.x;
    const int lane = tid & 31, wid = tid >> 5;
    const int wm = wid & 1, wn = wid >> 1;
    const int m0 = blockIdx.x * BM;
    const int n0 = blockIdx.y * BN;
    const int rd = iter & 1;

    const __nv_bfloat16* __restrict__ At =
        gAt[rd] + (size_t)((m0 >> 7) * 32) * 2 * 2048;
    const __nv_bfloat16* __restrict__ Bt =
        gBt + (size_t)iter * B_ELEMS + (size_t)((n0 >> 7) * 32) * 2 * 2048;

    uint32_t fullb[NSTG], emptyb[NSTG];
    #pragma unroll
    for (int s = 0; s < NSTG; s++) {
        fullb[s] = smem_u32(&s_full[s]);
        emptyb[s] = smem_u32(&s_empty[s]);
    }
    if (tid == 0) {
        #pragma unroll
        for (int s = 0; s < NSTG; s++) {
            MBAR_INIT(fullb[s], 1);
            MBAR_INIT(emptyb[s], 8);   // one arrive per warp per use
        }
    }
    __syncthreads();

    auto issue = [&](int ch) {
        int s = ch % NSTG;
        uint32_t dst = smem_u + s * STG_BYTES;
        MBAR_EXPECT_TX(fullb[s], STG_BYTES);
        bulk_g2s(dst,        At + (size_t)ch * 4096, 8192, fullb[s]);   // Ah|Al
        bulk_g2s(dst + 8192, Bt + (size_t)ch * 4096, 8192, fullb[s]);   // Bh|Bl
    };

    if (tid == 0) {
        #pragma unroll
        for (int ch = 0; ch < LOOKAHEAD; ch++) issue(ch);
    }

    int rowA[4], rowB[2];
    #pragma unroll
    for (int ms = 0; ms < 4; ms++)
        rowA[ms] = wm * 64 + ms * 16 + ((lane >> 3) & 1) * 8 + (lane & 7);
    #pragma unroll
    for (int nb = 0; nb < 2; nb++)
        rowB[nb] = wn * 32 + nb * 16 + ((lane >> 3) & 1) * 8 + (lane & 7);
    const int khalf = lane >> 4;   // 16B chunk 0/1

    float acc[4][4][4];
    #pragma unroll
    for (int i = 0; i < 4; i++)
        #pragma unroll
        for (int j = 0; j < 4; j++)
            #pragma unroll
            for (int q = 0; q < 4; q++) acc[i][j][q] = 0.f;

    for (int ch = 0; ch < NKCH; ch++) {
        const int s = ch % NSTG;
        // producer: refill stage (ch+LOOKAHEAD) once its consumers drained
        if (tid == 0 && ch + LOOKAHEAD < NKCH) {
            int tgt = ch + LOOKAHEAD;
            int ts = tgt % NSTG, rr = tgt / NSTG;
            if (rr >= 1) MBAR_WAIT(emptyb[ts], (rr - 1) & 1);
            issue(tgt);
        }

        MBAR_WAIT(fullb[s], (ch / NSTG) & 1);

        const uint32_t stbase = smem_u + s * STG_BYTES;
        uint32_t bh[2][4], bl[2][4];
        #pragma unroll
        for (int nb = 0; nb < 2; nb++) {
            uint32_t bd = stbase + 8192 + swz(rowB[nb], khalf);
            LDSM4(bh[nb], bd);
            LDSM4(bl[nb], bd + BLKB);
        }
        #pragma unroll
        for (int ms = 0; ms < 4; ms++) {
            uint32_t ah[4], al[4];
            uint32_t ad = stbase + swz(rowA[ms], khalf);
            LDSM4(ah, ad);
            LDSM4(al, ad + BLKB);
            #pragma unroll
            for (int ns = 0; ns < 4; ns++) {
                int nb = ns >> 1, od = ns & 1;
                mma_bf16(acc[ms][ns], ah, bh[nb][od], bh[nb][2 + od]);
                mma_bf16(acc[ms][ns], ah, bl[nb][od], bl[nb][2 + od]);
                mma_bf16(acc[ms][ns], al, bh[nb][od], bh[nb][2 + od]);
            }
        }
        __syncwarp();
        if (lane == 0) MBAR_ARRIVE(emptyb[s]);
    }

    // fused epilogue (no block barrier needed; regs only)
    const int nxt = (iter + 1) & 1;
    const int rowbase = m0 + wm * 64 + (lane >> 2);
    const int colbase = n0 + wn * 32 + (lane & 3) * 2;

    #pragma unroll
    for (int ms = 0; ms < 4; ms++) {
        #pragma unroll
        for (int ns = 0; ns < 4; ns++) {
            #pragma unroll
            for (int h = 0; h < 2; h++) {
                int row = rowbase + ms * 16 + h * 8;
                int col = colbase + ns * 8;
                float re = acc[ms][ns][2 * h];
                float im = acc[ms][ns][2 * h + 1];
                if (iter != NITER - 1) {
                    float phase = HALF_G * (re * re + im * im) + HALF_PHIB;
                    float sp, cp; __sincosf(phase, &sp, &cp);
                    float sc = SQ09 * cp;
                    float yre = sc * (cp * re + sp * im);
                    float yim = sc * (cp * im - sp * re);
                    __nv_bfloat16 hr = __float2bfloat16_rn(yre);
                    __nv_bfloat16 hi = __float2bfloat16_rn(yim);
                    __nv_bfloat16 lr = __float2bfloat16_rn(yre - __bfloat162float(hr));
                    __nv_bfloat16 li = __float2bfloat16_rn(yim - __bfloat162float(hi));
                    int mtile = row >> 7, r = row & 127;
                    int kch = col >> 4, cw = (col >> 3) & 1;
                    size_t base = (size_t)((mtile * 32 + kch) * 2) * 2048;
                    size_t off = (size_t)r * 16 + ((cw ^ ((r >> 2) & 1)) << 3)
                               + (col & 7);
                    *(__nv_bfloat162*)(gAt[nxt] + base + off) = __nv_bfloat162(hr, hi);
                    *(__nv_bfloat162*)(gAt[nxt] + base + 2048 + off) = __nv_bfloat162(lr, li);
                } else {
                    gV[(size_t)row * 256 + (col >> 1)] = re * re + im * im;
                }
            }
        }
    }
}

// ============================================================
// Kernel 6: row-wise L2 normalize of intensity, write 10 cols
// ============================================================
__global__ void normalize_kernel(float* __restrict__ out) {
    int w = (blockIdx.x * blockDim.x + threadIdx.x) >> 5;
    int lane = threadIdx.x & 31;
    if (w >= 8192) return;
    const float* v = gV + (size_t)w * 256;
    float first = 0.f, sum = 0.f;
    #pragma unroll
    for (int j = 0; j < 8; j++) {
        float x = v[lane + 32 * j];
        if (j == 0) first = x;
        sum += x * x;
    }
    #pragma unroll
    for (int o = 16; o; o >>= 1) sum += __shfl_xor_sync(0xFFFFFFFFu, sum, o);
    float inv = 1.f / fmaxf(sqrtf(sum), 1e-12f);
    if (lane < 10) out[w * 10 + lane] = first * inv;
}

// ============================================================
extern "C" void kernel_launch(void* const* d_in, const int* in_sizes, int n_in,
                              void* d_out, int out_size) {
    const float* xre   = (const float*)d_in[0];
    const float* xim   = (const float*)d_in[1];
    const float* theta = (const float*)d_in[2];
    const float* phi   = (const float*)d_in[3];
    const float* gamma = (const float*)d_in[4];
    float* out = (float*)d_out;

    static int attr_set = 0;
    if (!attr_set) {
        cudaFuncSetAttribute(gemm_kernel,
                             cudaFuncAttributeMaxDynamicSharedMemorySize, SMEM_DYN);
        attr_set = 1;
    }

    coef_kernel<<<(NITER * NWG * NP + 255) / 256, 256>>>(theta, phi);
    build_R_kernel<<<dim3(NWG / TBR, NITER), 512>>>(gamma);
    pack_W_kernel<<<(NITER * 512 * 64) / 256, 256>>>();
    prep_A_kernel<<<(8192 * 64) / 256, 256>>>(xre, xim);
    for (int it = 0; it < NITER; it++)
        gemm_kernel<<<dim3(8192 / BM, 512 / BN), 256, SMEM_DYN>>>(it);
    normalize_kernel<<<8192 / 8, 256>>>(out);
}

// round 9
// speedup vs baseline: 1.4106x; 1.4106x over previous
#include <cuda_runtime.h>
#include <cuda_fp16.h>
#include <math.h>
#include <stdint.h>

#define NWG   256
#define NP    128
#define NITER 3
#define TBR   4

#define HALF_G    0.07853981633974483f   // 0.5 * 0.05 * pi
#define HALF_PHIB 1.5707963267948966f    // 0.5 * pi
#define SQ09      0.9486832980505138f    // sqrt(1 - 0.1)

// GEMM tiling
#define BM 128
#define BN 128
#define BK 32
#define NKCH 16                          // 512 / 32
#define BLKB 8192                        // bytes per 128x32-fp16 pre-swizzled block
#define STG_BYTES (2 * BLKB)             // A|B = 16KB per stage
#define NSTG 3
#define SMEM_DYN (NSTG * STG_BYTES)      // 48KB

// Tiled global layouts: [tile][chunk 16][4096 fp16 pre-swizzled block]
#define A_ELEMS (64 * 16 * 4096)
#define B_ELEMS (4 * 16 * 4096)

// ---------------- device scratch (no allocs allowed) ----------------
__device__ float4 g_coef[NITER * NWG * NP * 2];
__device__ float  g_Rre[NITER * NWG * NWG];
__device__ float  g_Rim[NITER * NWG * NWG];
__device__ __half gBt[NITER * B_ELEMS];
__device__ __half gAt[2][A_ELEMS];
__device__ float gV[8192 * 256];

// ---------------- PTX helpers ----------------
__device__ __forceinline__ uint32_t smem_u32(const void* p) {
    return (uint32_t)__cvta_generic_to_shared(p);
}

#define LDSM4(r, addr)                                                         \
    asm volatile("ldmatrix.sync.aligned.m8n8.x4.shared.b16 {%0,%1,%2,%3}, [%4];" \
        : "=r"((r)[0]), "=r"((r)[1]), "=r"((r)[2]), "=r"((r)[3]) : "r"(addr))

__device__ __forceinline__ void mma_f16(float* d, const uint32_t* a,
                                        uint32_t b0, uint32_t b1) {
    asm volatile(
        "mma.sync.aligned.m16n8k16.row.col.f32.f16.f16.f32 "
        "{%0,%1,%2,%3}, {%4,%5,%6,%7}, {%8,%9}, {%0,%1,%2,%3};"
        : "+f"(d[0]), "+f"(d[1]), "+f"(d[2]), "+f"(d[3])
        : "r"(a[0]), "r"(a[1]), "r"(a[2]), "r"(a[3]), "r"(b0), "r"(b1));
}

__device__ __forceinline__ void bulk_g2s(uint32_t dst, const void* src,
                                         uint32_t bytes, uint32_t mb) {
    asm volatile(
        "cp.async.bulk.shared::cluster.global.mbarrier::complete_tx::bytes "
        "[%0], [%1], %2, [%3];"
        :: "r"(dst), "l"(src), "r"(bytes), "r"(mb) : "memory");
}
#define MBAR_INIT(mb, n) asm volatile("mbarrier.init.shared.b64 [%0], %1;" :: "r"(mb), "r"((uint32_t)(n)) : "memory")
#define MBAR_EXPECT_TX(mb, tx) asm volatile("mbarrier.arrive.expect_tx.shared.b64 _, [%0], %1;" :: "r"(mb), "r"((uint32_t)(tx)) : "memory")
#define FENCE_ASYNC() asm volatile("fence.proxy.async.shared::cta;" ::: "memory")

#define MBAR_WAIT(mb, par) do {                                                    \
    uint32_t _mb = (mb); uint32_t _p = (par); uint32_t _done;                      \
    asm volatile("{\n\t.reg .pred p;\n\t"                                          \
        "mbarrier.try_wait.parity.acquire.cta.shared::cta.b64 p, [%1], %2;\n\t"    \
        "selp.b32 %0, 1, 0, p;\n\t}"                                               \
        : "=r"(_done) : "r"(_mb), "r"(_p) : "memory");                             \
    if (!_done) {                                                                  \
        asm volatile("{\n\t.reg .pred P1;\n\t"                                     \
        "WL_%=:\n\t"                                                               \
        "mbarrier.try_wait.parity.acquire.cta.shared::cta.b64 P1, [%0], %1, 0x989680;\n\t" \
        "@P1 bra.uni WD_%=;\n\t"                                                   \
        "bra.uni WL_%=;\n\t"                                                       \
        "WD_%=:\n\t}" :: "r"(_mb), "r"(_p) : "memory");                            \
    } } while (0)

// swizzled byte offset within an 8KB block (row 0..127, 16B chunk c 0..3)
__device__ __forceinline__ uint32_t swz(int row, int c) {
    return (uint32_t)(row * 64 + ((c ^ ((row >> 1) & 3)) << 4));
}

// ============================================================
// Kernel 1: fold theta/phi into 2x2 complex MZI matrices
// ============================================================
__global__ void coef_kernel(const float* __restrict__ theta,
                            const float* __restrict__ phi) {
    int t = blockIdx.x * blockDim.x + threadIdx.x;
    const int total = NITER * NWG * NP;
    if (t >= total) return;
    int pair  = t % NP;
    int layer = (t / NP) % NWG;

    float4 c01, c23;
    if ((layer & 1) && pair == NP - 1) {
        c01 = make_float4(1.f, 0.f, 0.f, 0.f);
        c23 = make_float4(0.f, 0.f, 1.f, 0.f);
    } else {
        float h = 0.5f * theta[t];
        float s, c;  sincosf(h, &s, &c);
        float sp, cp; sincosf(phi[t], &sp, &cp);
        float pre_r = -s, pre_i = c;
        float pe_r = pre_r * cp - pre_i * sp;
        float pe_i = pre_r * sp + pre_i * cp;
        c01 = make_float4(pe_r * s,  pe_i * s,   pre_r * c,  pre_i * c);
        c23 = make_float4(pe_r * c,  pe_i * c,  -pre_r * s, -pre_i * s);
    }
    g_coef[2 * t]     = c01;
    g_coef[2 * t + 1] = c23;
}

// ============================================================
// Kernel 2: build R via identity basis. grid (64, 3), block 512.
// ============================================================
__global__ void build_R_kernel(const float* __restrict__ gamma) {
    __shared__ float x0r[TBR][NP], x0i[TBR][NP], x1r[TBR][NP], x1i[TBR][NP];
    const int iter = blockIdx.y;
    const int p = threadIdx.x & (NP - 1);
    const int r = threadIdx.x >> 7;
    const int gj = blockIdx.x * TBR + r;

    x0r[r][p] = (2 * p     == gj) ? 1.f : 0.f;  x0i[r][p] = 0.f;
    x1r[r][p] = (2 * p + 1 == gj) ? 1.f : 0.f;  x1i[r][p] = 0.f;
    __syncthreads();

    const float4* cbase = g_coef + (size_t)iter * NWG * NP * 2;
    for (int l = 0; l < NWG; l++) {
        float4 c01 = cbase[(l * NP + p) * 2];
        float4 c23 = cbase[(l * NP + p) * 2 + 1];
        float Ar = c01.x, Ai = c01.y, Br = c01.z, Bi = c01.w;
        float Cr = c23.x, Ci = c23.y, Dr = c23.z, Di = c23.w;
        if (!(l & 1)) {
            float ar = x0r[r][p], ai = x0i[r][p];
            float br = x1r[r][p], bi = x1i[r][p];
            x0r[r][p] = Ar*ar - Ai*ai + Br*br - Bi*bi;
            x0i[r][p] = Ar*ai + Ai*ar + Br*bi + Bi*br;
            x1r[r][p] = Cr*ar - Ci*ai + Dr*br - Di*bi;
            x1i[r][p] = Cr*ai + Ci*ar + Dr*bi + Di*br;
        } else if (p < NP - 1) {
            float ar = x1r[r][p],     ai = x1i[r][p];
            float br = x0r[r][p + 1], bi = x0i[r][p + 1];
            float y0r = Ar*ar - Ai*ai + Br*br - Bi*bi;
            float y0i = Ar*ai + Ai*ar + Br*bi + Bi*br;
            float y1r = Cr*ar - Ci*ai + Dr*br - Di*bi;
            float y1i = Cr*ai + Ci*ar + Dr*bi + Di*br;
            x1r[r][p] = y0r;     x1i[r][p] = y0i;
            x0r[r][p + 1] = y1r; x0i[r][p + 1] = y1i;
        }
        __syncthreads();
    }

    float s0, c0, s1, c1;
    sincosf(gamma[iter * NWG + 2 * p],     &s0, &c0);
    sincosf(gamma[iter * NWG + 2 * p + 1], &s1, &c1);
    size_t rowoff = ((size_t)iter * NWG + gj) * NWG;
    float xr = x0r[r][p], xi = x0i[r][p];
    g_Rre[rowoff + 2 * p] = xr * c0 - xi * s0;
    g_Rim[rowoff + 2 * p] = xr * s0 + xi * c0;
    xr = x1r[r][p]; xi = x1i[r][p];
    g_Rre[rowoff + 2 * p + 1] = xr * c1 - xi * s1;
    g_Rim[rowoff + 2 * p + 1] = xr * s1 + xi * c1;
}

// ============================================================
// Kernel 3: pack W^T into tiled, pre-swizzled fp16 blocks.
// W[2a][2c]=Rr, W[2a+1][2c]=-Ri, W[2a][2c+1]=Ri, W[2a+1][2c+1]=Rr
// thread: (it, n, kq); kq = 16B group (8 k values).
// ============================================================
__global__ void pack_W_kernel() {
    int t = blockIdx.x * blockDim.x + threadIdx.x;
    if (t >= NITER * 512 * 64) return;
    int kq = t & 63;
    int n  = (t >> 6) & 511;
    int it = t >> 15;
    int c = n >> 1, nb = n & 1;

    __align__(16) __half hb[8];
    #pragma unroll
    for (int q = 0; q < 8; q++) {
        int k = kq * 8 + q;
        int a = k >> 1, kb = k & 1;
        size_t ri = ((size_t)it * NWG + a) * NWG + c;
        float val;
        if (kb == nb)      val = g_Rre[ri];
        else if (kb == 1)  val = -g_Rim[ri];
        else               val = g_Rim[ri];
        hb[q] = __float2half_rn(val);
    }
    int ntile = n >> 7, r = n & 127;
    int chunk = kq >> 2, cw = kq & 3;
    size_t base = (size_t)it * B_ELEMS + (size_t)(ntile * 16 + chunk) * 4096;
    size_t off = (size_t)r * 32 + ((cw ^ ((r >> 1) & 3)) << 3);
    *(uint4*)(gBt + base + off) = *(const uint4*)hb;
}

// ============================================================
// Kernel 4: prep A0 into tiled, pre-swizzled fp16 layout.
// ============================================================
__global__ void prep_A_kernel(const float* __restrict__ xr,
                              const float* __restrict__ xi) {
    int t = blockIdx.x * blockDim.x + threadIdx.x;
    if (t >= 8192 * 64) return;
    int cq = t & 63, m = t >> 6;
    float4 vr = *(const float4*)(xr + (size_t)m * 256 + cq * 4);
    float4 vi = *(const float4*)(xi + (size_t)m * 256 + cq * 4);
    float re[4] = { vr.x, vr.y, vr.z, vr.w };
    float im[4] = { vi.x, vi.y, vi.z, vi.w };
    __align__(16) __half hb[8];
    #pragma unroll
    for (int q = 0; q < 4; q++) {
        hb[2 * q]     = __float2half_rn(re[q]);
        hb[2 * q + 1] = __float2half_rn(im[q]);
    }
    int mtile = m >> 7, r = m & 127;
    int chunk = cq >> 2, cw = cq & 3;
    size_t base = (size_t)(mtile * 16 + chunk) * 4096;
    size_t off = (size_t)r * 32 + ((cw ^ ((r >> 1) & 3)) << 3);
    *(uint4*)(gAt[0] + base + off) = *(const uint4*)hb;
}

// ============================================================
// Kernel 5: fp16 GEMM (mma.sync, f32 acc) + fused epilogue.
// grid (64, 4), 256 threads, 2 CTAs/SM. Lockstep 3-stage bulk pipeline.
// ============================================================
__global__ void __launch_bounds__(256, 2) gemm_kernel(int iter) {
    extern __shared__ char smraw[];
    __shared__ __align__(8) unsigned long long s_mbar[NSTG];
    const uint32_t smem_u = (uint32_t)__cvta_generic_to_shared(smraw);

    const int tid = threadIdx.x;
    const int lane = tid & 31, wid = tid >> 5;
    const int wm = wid & 1, wn = wid >> 1;
    const int m0 = blockIdx.x * BM;
    const int n0 = blockIdx.y * BN;
    const int rd = iter & 1;

    const __half* __restrict__ At = gAt[rd] + (size_t)((m0 >> 7) * 16) * 4096;
    const __half* __restrict__ Bt =
        gBt + (size_t)iter * B_ELEMS + (size_t)((n0 >> 7) * 16) * 4096;

    uint32_t mb[NSTG];
    #pragma unroll
    for (int s = 0; s < NSTG; s++) mb[s] = smem_u32(&s_mbar[s]);
    if (tid == 0) {
        #pragma unroll
        for (int s = 0; s < NSTG; s++) MBAR_INIT(mb[s], 1);
    }
    __syncthreads();

    auto issue = [&](int ch) {
        int s = ch % NSTG;
        uint32_t dst = smem_u + s * STG_BYTES;
        MBAR_EXPECT_TX(mb[s], STG_BYTES);
        bulk_g2s(dst,        At + (size_t)ch * 4096, BLKB, mb[s]);   // A block
        bulk_g2s(dst + BLKB, Bt + (size_t)ch * 4096, BLKB, mb[s]);   // B block
    };

    if (tid == 0) { issue(0); issue(1); }

    int rowA[4], rowB[2];
    #pragma unroll
    for (int ms = 0; ms < 4; ms++)
        rowA[ms] = wm * 64 + ms * 16 + ((lane >> 3) & 1) * 8 + (lane & 7);
    #pragma unroll
    for (int nb = 0; nb < 2; nb++)
        rowB[nb] = wn * 32 + nb * 16 + ((lane >> 3) & 1) * 8 + (lane & 7);
    const int khalf = lane >> 4;   // 0/1

    float acc[4][4][4];
    #pragma unroll
    for (int i = 0; i < 4; i++)
        #pragma unroll
        for (int j = 0; j < 4; j++)
            #pragma unroll
            for (int q = 0; q < 4; q++) acc[i][j][q] = 0.f;

    for (int ch = 0; ch < NKCH; ch++) {
        const int b = ch % NSTG;
        MBAR_WAIT(mb[b], (ch / NSTG) & 1);
        __syncthreads();   // all threads done with stage ch-1 -> refillable
        if (tid == 0 && ch + 2 < NKCH) { FENCE_ASYNC(); issue(ch + 2); }

        const uint32_t stbase = smem_u + b * STG_BYTES;
        #pragma unroll
        for (int kk = 0; kk < 2; kk++) {
            const int kidx = kk * 2 + khalf;
            uint32_t bh[2][4];
            #pragma unroll
            for (int nb = 0; nb < 2; nb++)
                LDSM4(bh[nb], stbase + BLKB + swz(rowB[nb], kidx));
            #pragma unroll
            for (int ms = 0; ms < 4; ms++) {
                uint32_t ah[4];
                LDSM4(ah, stbase + swz(rowA[ms], kidx));
                #pragma unroll
                for (int ns = 0; ns < 4; ns++) {
                    int nb = ns >> 1, od = ns & 1;
                    mma_f16(acc[ms][ns], ah, bh[nb][od], bh[nb][2 + od]);
                }
            }
        }
    }

    // fused epilogue (fragment (re,im) pairs are thread-local)
    const int nxt = (iter + 1) & 1;
    const int rowbase = m0 + wm * 64 + (lane >> 2);
    const int colbase = n0 + wn * 32 + (lane & 3) * 2;

    #pragma unroll
    for (int ms = 0; ms < 4; ms++) {
        #pragma unroll
        for (int ns = 0; ns < 4; ns++) {
            #pragma unroll
            for (int h = 0; h < 2; h++) {
                int row = rowbase + ms * 16 + h * 8;
                int col = colbase + ns * 8;
                float re = acc[ms][ns][2 * h];
                float im = acc[ms][ns][2 * h + 1];
                if (iter != NITER - 1) {
                    float phase = HALF_G * (re * re + im * im) + HALF_PHIB;
                    float sp, cp; __sincosf(phase, &sp, &cp);
                    float sc = SQ09 * cp;
                    float yre = sc * (cp * re + sp * im);
                    float yim = sc * (cp * im - sp * re);
                    int mtile = row >> 7, r = row & 127;
                    int chunk = col >> 5, cw = (col >> 3) & 3;
                    size_t base = (size_t)(mtile * 16 + chunk) * 4096;
                    size_t off = (size_t)r * 32 + ((cw ^ ((r >> 1) & 3)) << 3)
                               + (col & 7);
                    *(__half2*)(gAt[nxt] + base + off) =
                        __half2(__float2half_rn(yre), __float2half_rn(yim));
                } else {
                    gV[(size_t)row * 256 + (col >> 1)] = re * re + im * im;
                }
            }
        }
    }
}

// ============================================================
// Kernel 6: row-wise L2 normalize of intensity, write 10 cols
// ============================================================
__global__ void normalize_kernel(float* __restrict__ out) {
    int w = (blockIdx.x * blockDim.x + threadIdx.x) >> 5;
    int lane = threadIdx.x & 31;
    if (w >= 8192) return;
    const float* v = gV + (size_t)w * 256;
    float first = 0.f, sum = 0.f;
    #pragma unroll
    for (int j = 0; j < 8; j++) {
        float x = v[lane + 32 * j];
        if (j == 0) first = x;
        sum += x * x;
    }
    #pragma unroll
    for (int o = 16; o; o >>= 1) sum += __shfl_xor_sync(0xFFFFFFFFu, sum, o);
    float inv = 1.f / fmaxf(sqrtf(sum), 1e-12f);
    if (lane < 10) out[w * 10 + lane] = first * inv;
}

// ============================================================
extern "C" void kernel_launch(void* const* d_in, const int* in_sizes, int n_in,
                              void* d_out, int out_size) {
    const float* xre   = (const float*)d_in[0];
    const float* xim   = (const float*)d_in[1];
    const float* theta = (const float*)d_in[2];
    const float* phi   = (const float*)d_in[3];
    const float* gamma = (const float*)d_in[4];
    float* out = (float*)d_out;

    static int attr_set = 0;
    if (!attr_set) {
        cudaFuncSetAttribute(gemm_kernel,
                             cudaFuncAttributeMaxDynamicSharedMemorySize, SMEM_DYN);
        attr_set = 1;
    }

    coef_kernel<<<(NITER * NWG * NP + 255) / 256, 256>>>(theta, phi);
    build_R_kernel<<<dim3(NWG / TBR, NITER), 512>>>(gamma);
    pack_W_kernel<<<(NITER * 512 * 64) / 256, 256>>>();
    prep_A_kernel<<<(8192 * 64) / 256, 256>>>(xre, xim);
    for (int it = 0; it < NITER; it++)
        gemm_kernel<<<dim3(8192 / BM, 512 / BN), 256, SMEM_DYN>>>(it);
    normalize_kernel<<<8192 / 8, 256>>>(out);
}